// round 9
// baseline (speedup 1.0000x reference)
#include <cuda_runtime.h>
#include <cstdint>

#define NN 100000
#define NE 1000000
#define NB 500000
#define H  16
#define RND 5

#define SQ 258   // float4 pitch (258 % 8 == 2 -> conflict-free)

typedef unsigned long long ull;

// ---------------- scratch ---------------------------------------------------
__device__ __align__(16) float g_nf[NN * H];
__device__ __align__(16) float g_ef[NE * H];
__device__ __align__(16) float g_pre_s[NN * H];   // W1[:,0:16]  @ nf
__device__ __align__(16) float g_pre_r[NN * H];   // W1[:,16:32] @ nf + b1
__device__ __align__(16) float g_agg[NN * H];
__device__ float g_deg[NN];
__device__ int   g_win[NE];

// ---------------- helpers ---------------------------------------------------
__device__ __forceinline__ ull pk(float a, float b) {
    ull r; asm("mov.b64 %0,{%1,%2};" : "=l"(r) : "f"(a), "f"(b)); return r;
}
__device__ __forceinline__ float2 upk(ull a) {
    float2 f; asm("mov.b64 {%0,%1},%2;" : "=f"(f.x), "=f"(f.y) : "l"(a)); return f;
}
__device__ __forceinline__ ull fma2(ull a, ull b, ull c) {
    ull d; asm("fma.rn.f32x2 %0,%1,%2,%3;" : "=l"(d) : "l"(a), "l"(b), "l"(c)); return d;
}

__device__ __forceinline__ void ld16(const float* __restrict__ p, float* f) {
    const float4* q = (const float4*)p;
    float4 a = q[0], b = q[1], c = q[2], d = q[3];
    f[0]=a.x; f[1]=a.y; f[2]=a.z; f[3]=a.w;
    f[4]=b.x; f[5]=b.y; f[6]=b.z; f[7]=b.w;
    f[8]=c.x; f[9]=c.y; f[10]=c.z; f[11]=c.w;
    f[12]=d.x; f[13]=d.y; f[14]=d.z; f[15]=d.w;
}
__device__ __forceinline__ void st16(float* __restrict__ p, const float* f) {
    float4* q = (float4*)p;
    q[0] = make_float4(f[0], f[1], f[2], f[3]);
    q[1] = make_float4(f[4], f[5], f[6], f[7]);
    q[2] = make_float4(f[8], f[9], f[10], f[11]);
    q[3] = make_float4(f[12], f[13], f[14], f[15]);
}
__device__ __forceinline__ void red_add4(float* p, float4 v) {
    asm volatile("red.global.add.v4.f32 [%0], {%1,%2,%3,%4};"
                 :: "l"(p), "f"(v.x), "f"(v.y), "f"(v.z), "f"(v.w) : "memory");
}
__device__ __forceinline__ void red_deg(float* p) {
    asm volatile("red.global.add.f32 [%0], %1;" :: "l"(p), "f"(1.0f) : "memory");
}

__device__ __forceinline__ void pack8(const float* f, ull* xp) {
#pragma unroll
    for (int kk = 0; kk < 8; kk++) xp[kk] = pk(f[2*kk], f[2*kk+1]);
}

// single-vector 16-out GEMV, weights from smem as float4 (k-packed)
__device__ __forceinline__ void single16(const float4* __restrict__ w4, const ull* xp,
                                         const float* init, float* o, bool relu) {
#pragma unroll
    for (int oo = 0; oo < 16; oo++) {
        ull a = 0ULL;
#pragma unroll
        for (int q = 0; q < 4; q++) {
            float4 wv = w4[oo*4 + q];
            a = fma2(pk(wv.x, wv.y), xp[2*q],   a);
            a = fma2(pk(wv.z, wv.w), xp[2*q+1], a);
        }
        float2 f = upk(a);
        float v = init[oo] + f.x + f.y;
        o[oo] = relu ? fmaxf(v, 0.0f) : v;
    }
}

// dual-vector 16-out GEMVs (node kernels)
__device__ __forceinline__ void dual16(const float4* __restrict__ w4,
                                       const ull* xpA, const ull* xpB,
                                       const float* initA, const float* initB,
                                       float* oA, float* oB, bool relu) {
#pragma unroll
    for (int oo = 0; oo < 16; oo++) {
        ull aA = 0ULL, aB = 0ULL;
#pragma unroll
        for (int q = 0; q < 4; q++) {
            float4 wv = w4[oo*4 + q];
            ull w0 = pk(wv.x, wv.y), w1 = pk(wv.z, wv.w);
            aA = fma2(w0, xpA[2*q], aA); aA = fma2(w1, xpA[2*q+1], aA);
            aB = fma2(w0, xpB[2*q], aB); aB = fma2(w1, xpB[2*q+1], aB);
        }
        float2 fA = upk(aA), fB = upk(aB);
        float vA = initA[oo] + fA.x + fA.y;
        float vB = initB[oo] + fB.x + fB.y;
        oA[oo] = relu ? fmaxf(vA, 0.0f) : vA;
        oB[oo] = relu ? fmaxf(vB, 0.0f) : vB;
    }
}

__device__ __forceinline__ void dual16_k16(const float4* __restrict__ w4,
                                           const ull* xpA, const ull* xpB,
                                           const float* initA, const float* initB,
                                           float* oA, float* oB, bool relu) {
#pragma unroll
    for (int oo = 0; oo < 16; oo++) {
        ull aA = 0ULL, aB = 0ULL;
#pragma unroll
        for (int q = 0; q < 8; q++) {
            float4 wv = w4[oo*8 + q];
            ull w0 = pk(wv.x, wv.y), w1 = pk(wv.z, wv.w);
            aA = fma2(w0, xpA[2*q], aA); aA = fma2(w1, xpA[2*q+1], aA);
            aB = fma2(w0, xpB[2*q], aB); aB = fma2(w1, xpB[2*q+1], aB);
        }
        float2 fA = upk(aA), fB = upk(aB);
        float vA = initA[oo] + fA.x + fA.y;
        float vB = initB[oo] + fB.x + fB.y;
        oA[oo] = relu ? fmaxf(vA, 0.0f) : vA;
        oB[oo] = relu ? fmaxf(vB, 0.0f) : vB;
    }
}

// ---------------- kernels ----------------------------------------------------
// node encoder: scalar->h->h, plus round-0 pre_s/pre_r, agg zeroing, deg zeroing
__global__ void k_encode_node(const float* __restrict__ x,
                              const float* __restrict__ W1, const float* __restrict__ b1,
                              const float* __restrict__ W2, const float* __restrict__ b2,
                              const float* __restrict__ mpW1, const float* __restrict__ mpB1) {
    __shared__ __align__(16) ull sW2p[128], sPSp[128], sPRp[128];
    __shared__ float sW1[16], sB1[16], sB2[16], sB1n[16], sZ[16];
    int tid = threadIdx.x;
    if (tid < 128) {
        int oo = tid >> 3, kk = tid & 7;
        sW2p[tid] = pk(W2[oo*16 + 2*kk],        W2[oo*16 + 2*kk + 1]);
        sPSp[tid] = pk(mpW1[oo*48 + 2*kk],      mpW1[oo*48 + 2*kk + 1]);
        sPRp[tid] = pk(mpW1[oo*48 + 16 + 2*kk], mpW1[oo*48 + 16 + 2*kk + 1]);
    }
    if (tid < 16) {
        sW1[tid] = W1[tid]; sB1[tid] = b1[tid]; sB2[tid] = b2[tid];
        sB1n[tid] = mpB1[tid]; sZ[tid] = 0.0f;
    }
    __syncthreads();
    int n = blockIdx.x * blockDim.x + tid;
    if (n >= NN) return;
    g_deg[n] = 0.0f;
    float xv = x[n];
    float h[16];
#pragma unroll
    for (int k = 0; k < 16; k++) h[k] = fmaxf(sW1[k] * xv + sB1[k], 0.0f);
    ull hp[8]; pack8(h, hp);
    float nf[16];
    single16((const float4*)sW2p, hp, sB2, nf, false);
    st16(&g_nf[(size_t)n * 16], nf);
    ull np[8]; pack8(nf, np);
    float ps[16], pr[16];
    single16((const float4*)sPSp, np, sZ,   ps, false);
    single16((const float4*)sPRp, np, sB1n, pr, false);
    st16(&g_pre_s[(size_t)n * 16], ps);
    st16(&g_pre_r[(size_t)n * 16], pr);
    float z[16];
#pragma unroll
    for (int k = 0; k < 16; k++) z[k] = 0.0f;
    st16(&g_agg[(size_t)n * 16], z);
}

// edge encoder: scalar->h->h, degree count, win init
__global__ void __launch_bounds__(256, 4)
k_encode_edge(const float* __restrict__ x,
              const float* __restrict__ W1, const float* __restrict__ b1,
              const float* __restrict__ W2, const float* __restrict__ b2,
              const int* __restrict__ recv) {
    __shared__ __align__(16) ull sW2p[128];
    __shared__ float sW1[16], sB1[16], sB2[16];
    int tid = threadIdx.x;
    if (tid < 128) {
        int oo = tid >> 3, kk = tid & 7;
        sW2p[tid] = pk(W2[oo*16 + 2*kk], W2[oo*16 + 2*kk + 1]);
    }
    if (tid < 16) { sW1[tid] = W1[tid]; sB1[tid] = b1[tid]; sB2[tid] = b2[tid]; }
    __syncthreads();
    int e = blockIdx.x * blockDim.x + tid;
    if (e >= NE) return;
    g_win[e] = -1;
    float xv = x[e];
    float h[16];
#pragma unroll
    for (int k = 0; k < 16; k++) h[k] = fmaxf(sW1[k] * xv + sB1[k], 0.0f);
    ull hp[8]; pack8(h, hp);
    float ef[16];
    single16((const float4*)sW2p, hp, sB2, ef, false);
    st16(&g_ef[(size_t)e * 16], ef);
    red_deg(&g_deg[recv[e]]);
}

// per-round edge update: R8 structure (256-edge tile, paired compute sharing
// weight LDS), but PLAIN global accesses so the 91MB working set (ef + pre +
// agg + indices) stays L2-resident across rounds. Round 0 additionally runs
// the bi-edge winner election in its tail (g_win initialized by encoder).
__global__ void __launch_bounds__(256, 4)
k_edge(const int* __restrict__ snd, const int* __restrict__ rcv,
       const float* __restrict__ W1, const float* __restrict__ W2,
       const float* __restrict__ b2, const int* __restrict__ bi) {
    __shared__ __align__(16) float4 sE[4 * SQ];
    __shared__ __align__(16) float4 sP[4 * SQ];
    __shared__ __align__(16) ull sW1t[128];   // [k][jpair]: outs (2j,2j+1), k of ef-part
    __shared__ __align__(16) ull sW2t[128];   // [g][k][j2]: outs (4g+2j2, 4g+2j2+1)
    __shared__ __align__(16) ull sB2p[8];

    int tid = threadIdx.x;
    int base = blockIdx.x * 256;
    int nE = NE - base; if (nE > 256) nE = 256;

    if (tid < 128) {
        int k = tid >> 3, j = tid & 7;
        sW1t[k * 8 + j] = pk(W1[(2*j)*48 + 32 + k], W1[(2*j+1)*48 + 32 + k]);
        int g = tid >> 5, rem = tid & 31;
        int kk = rem >> 1, j2 = rem & 1;
        sW2t[tid] = pk(W2[(4*g + 2*j2)*16 + kk], W2[(4*g + 2*j2 + 1)*16 + kk]);
    }
    if (tid < 8) sB2p[tid] = pk(b2[2*tid], b2[2*tid+1]);

    const float4* gE = (const float4*)g_ef + (size_t)base * 4;
    const float4* gS = (const float4*)g_pre_s;
    const float4* gR = (const float4*)g_pre_r;
#pragma unroll
    for (int j = 0; j < 4; j++) {
        int g = j * 256 + tid;
        int e = g >> 2, seg = g & 3;
        if (e < nE) {
            sE[seg * SQ + e] = gE[g];
            int ns = snd[base + e];
            int nr = rcv[base + e];
            float4 a = gS[(size_t)ns * 4 + seg];
            float4 b = gR[(size_t)nr * 4 + seg];
            sP[seg * SQ + e] = make_float4(a.x + b.x, a.y + b.y, a.z + b.z, a.w + b.w);
        }
    }
    __syncthreads();

    if (tid < 128) {
        int eA = tid, eB = tid + 128;

        // ---- layer 1: out-packed accumulators, shared weight loads ----
        ull accA[8], accB[8];
#pragma unroll
        for (int j = 0; j < 8; j++) { accA[j] = 0ULL; accB[j] = 0ULL; }
#pragma unroll
        for (int c = 0; c < 4; c++) {
            float4 xvA = sE[c * SQ + eA];
            float4 xvB = sE[c * SQ + eB];
            const float* xa = (const float*)&xvA;
            const float* xb = (const float*)&xvB;
#pragma unroll
            for (int t = 0; t < 4; t++) {
                int k = 4*c + t;
                ull xxA = pk(xa[t], xa[t]);
                ull xxB = pk(xb[t], xb[t]);
                const ull* wr = &sW1t[k * 8];
#pragma unroll
                for (int j = 0; j < 8; j++) {
                    ull wv = wr[j];
                    accA[j] = fma2(wv, xxA, accA[j]);
                    accB[j] = fma2(wv, xxB, accB[j]);
                }
            }
        }
        // ---- finish layer 1: bias(pre) + relu -> scalar h ----
        float hA[16], hB[16];
#pragma unroll
        for (int c = 0; c < 4; c++) {
            float4 pA = sP[c * SQ + eA];
            float4 pB = sP[c * SQ + eB];
            float2 a0 = upk(accA[2*c]), a1 = upk(accA[2*c+1]);
            float2 b0 = upk(accB[2*c]), b1 = upk(accB[2*c+1]);
            hA[4*c+0] = fmaxf(a0.x + pA.x, 0.0f);
            hA[4*c+1] = fmaxf(a0.y + pA.y, 0.0f);
            hA[4*c+2] = fmaxf(a1.x + pA.z, 0.0f);
            hA[4*c+3] = fmaxf(a1.y + pA.w, 0.0f);
            hB[4*c+0] = fmaxf(b0.x + pB.x, 0.0f);
            hB[4*c+1] = fmaxf(b0.y + pB.y, 0.0f);
            hB[4*c+2] = fmaxf(b1.x + pB.z, 0.0f);
            hB[4*c+3] = fmaxf(b1.y + pB.w, 0.0f);
        }
        // ---- layer 2: out-chunked, shared weight loads ----
#pragma unroll
        for (int g = 0; g < 4; g++) {
            ull aA0 = 0ULL, aA1 = 0ULL, aB0 = 0ULL, aB1 = 0ULL;
            const ull* w2 = &sW2t[g * 32];
#pragma unroll
            for (int k = 0; k < 16; k++) {
                ull w0 = w2[2*k], w1 = w2[2*k+1];
                ull xxA = pk(hA[k], hA[k]);
                ull xxB = pk(hB[k], hB[k]);
                aA0 = fma2(w0, xxA, aA0); aA1 = fma2(w1, xxA, aA1);
                aB0 = fma2(w0, xxB, aB0); aB1 = fma2(w1, xxB, aB1);
            }
            float2 f0 = upk(aA0), f1 = upk(aA1);
            float2 g0 = upk(aB0), g1 = upk(aB1);
            float2 c0 = upk(sB2p[2*g]), c1 = upk(sB2p[2*g+1]);
            sE[g * SQ + eA] = make_float4(f0.x + c0.x, f0.y + c0.y, f1.x + c1.x, f1.y + c1.y);
            sE[g * SQ + eB] = make_float4(g0.x + c0.x, g0.y + c0.y, g1.x + c1.x, g1.y + c1.y);
        }
    }
    __syncthreads();

    // coalesced store + grouped scatter
    float4* gEo = (float4*)g_ef + (size_t)base * 4;
#pragma unroll
    for (int j = 0; j < 4; j++) {
        int g = j * 256 + tid;
        int e = g >> 2, seg = g & 3;
        if (e < nE) {
            float4 v = sE[seg * SQ + e];
            gEo[g] = v;
            int nr = rcv[base + e];
            red_add4(&g_agg[(size_t)nr * 16 + seg * 4], v);
        }
    }

    // round 0 only: bi-edge winner election folded into the tail
    if (bi) {
        int p = base + tid;
        if (p < NB) {
            atomicMax(&g_win[bi[p]], p);
            atomicMax(&g_win[bi[NB + p]], (1 << 30) | p);
        }
    }
}

// per-round node update, TWO nodes per thread; also computes pre for next round
__global__ void k_node_upd(const float* __restrict__ W1, const float* __restrict__ b1,
                           const float* __restrict__ W2, const float* __restrict__ b2,
                           const float* __restrict__ nW1, const float* __restrict__ nB1,
                           int has_next) {
    __shared__ __align__(16) ull sW1p[256], sW2p[128], sPSp[128], sPRp[128];
    __shared__ float sB1[16], sB2[16], sB1n[16], sZ[16];
    int tid = threadIdx.x;
    {
        int oo = tid >> 4, kk = tid & 15;
        sW1p[tid] = pk(W1[oo*32 + 2*kk], W1[oo*32 + 2*kk + 1]);
    }
    if (tid < 128) {
        int oo = tid >> 3, kk = tid & 7;
        sW2p[tid] = pk(W2[oo*16 + 2*kk], W2[oo*16 + 2*kk + 1]);
        if (has_next) {
            sPSp[tid] = pk(nW1[oo*48 + 2*kk],      nW1[oo*48 + 2*kk + 1]);
            sPRp[tid] = pk(nW1[oo*48 + 16 + 2*kk], nW1[oo*48 + 16 + 2*kk + 1]);
        }
    }
    if (tid < 16) {
        sB1[tid] = b1[tid]; sB2[tid] = b2[tid];
        sB1n[tid] = has_next ? nB1[tid] : 0.0f;
        sZ[tid] = 0.0f;
    }
    __syncthreads();
    int t = blockIdx.x * blockDim.x + tid;
    if (t >= NN / 2) return;
    int n0 = 2 * t, n1 = 2 * t + 1;

    float fA[16], fB[16], aA[16], aB[16];
    ld16(&g_nf[(size_t)n0 * 16], fA);
    ld16(&g_nf[(size_t)n1 * 16], fB);
    ld16(&g_agg[(size_t)n0 * 16], aA);
    ld16(&g_agg[(size_t)n1 * 16], aB);
    float ivA = 1.0f / fmaxf(g_deg[n0], 1.0f);
    float ivB = 1.0f / fmaxf(g_deg[n1], 1.0f);
#pragma unroll
    for (int k = 0; k < 16; k++) { aA[k] *= ivA; aB[k] *= ivB; }

    ull xpA[16], xpB[16];
    pack8(fA, xpA); pack8(aA, xpA + 8);
    pack8(fB, xpB); pack8(aB, xpB + 8);

    float hA[16], hB[16];
    dual16_k16((const float4*)sW1p, xpA, xpB, sB1, sB1, hA, hB, true);
    ull hpA[8], hpB[8];
    pack8(hA, hpA); pack8(hB, hpB);
    float oA[16], oB[16];
    dual16((const float4*)sW2p, hpA, hpB, sB2, sB2, oA, oB, false);
    st16(&g_nf[(size_t)n0 * 16], oA);
    st16(&g_nf[(size_t)n1 * 16], oB);

    if (has_next) {
        ull opA[8], opB[8];
        pack8(oA, opA); pack8(oB, opB);
        float psA[16], psB[16], prA[16], prB[16];
        dual16((const float4*)sPSp, opA, opB, sZ, sZ, psA, psB, false);
        dual16((const float4*)sPRp, opA, opB, sB1n, sB1n, prA, prB, false);
        st16(&g_pre_s[(size_t)n0 * 16], psA);
        st16(&g_pre_s[(size_t)n1 * 16], psB);
        st16(&g_pre_r[(size_t)n0 * 16], prA);
        st16(&g_pre_r[(size_t)n1 * 16], prB);
        float z[16];
#pragma unroll
        for (int k = 0; k < 16; k++) z[k] = 0.0f;
        st16(&g_agg[(size_t)n0 * 16], z);
        st16(&g_agg[(size_t)n1 * 16], z);
    }
}

// decode: bi-average from pre-decode ef, MLP h->h->1, tril mask
__global__ void __launch_bounds__(256, 4)
k_dec(const int* __restrict__ snd, const int* __restrict__ rcv,
      const int* __restrict__ bi,
      const float* __restrict__ W1, const float* __restrict__ b1,
      const float* __restrict__ W2, const float* __restrict__ b2,
      float* __restrict__ out, int write_extra) {
    __shared__ __align__(16) ull sW1p[128];
    __shared__ float sB1[16], sW2[16], sB2;
    int tid = threadIdx.x;
    if (tid < 128) {
        int oo = tid >> 3, kk = tid & 7;
        sW1p[tid] = pk(W1[oo*16 + 2*kk], W1[oo*16 + 2*kk + 1]);
    }
    if (tid < 16) { sB1[tid] = b1[tid]; sW2[tid] = W2[tid]; }
    if (tid == 0) sB2 = b2[0];
    __syncthreads();
    int e = blockIdx.x * blockDim.x + tid;
    if (e >= NE) return;
    float f[16];
    int w = g_win[e];
    if (w >= 0) {
        int p = w & 0x3FFFFFFF;
        int i = bi[p], j = bi[NB + p];
        float fi[16], fj[16];
        ld16(&g_ef[(size_t)i * 16], fi);
        ld16(&g_ef[(size_t)j * 16], fj);
#pragma unroll
        for (int k = 0; k < 16; k++) f[k] = 0.5f * (fi[k] + fj[k]);
    } else {
        ld16(&g_ef[(size_t)e * 16], f);
    }
    ull fp[8]; pack8(f, fp);
    float h[16];
    single16((const float4*)sW1p, fp, sB1, h, true);
    float val = sB2;
#pragma unroll
    for (int o = 0; o < 16; o++) val += sW2[o] * h[o];
    int s = snd[e], r = rcv[e];
    out[e] = (r >= s) ? val : 0.0f;
    if (write_extra) {
        out[NE + e] = (float)r;
        out[2 * NE + e] = (float)s;
    }
}

// ---------------- launch -----------------------------------------------------
extern "C" void kernel_launch(void* const* d_in, const int* in_sizes, int n_in,
                              void* d_out, int out_size) {
    const float* nodes    = (const float*)d_in[0];
    const float* edges    = (const float*)d_in[1];
    const int*   receivers= (const int*)d_in[2];
    const int*   senders  = (const int*)d_in[3];
    const int*   bi       = (const int*)d_in[4];
    const float* neW1 = (const float*)d_in[5];
    const float* neB1 = (const float*)d_in[6];
    const float* neW2 = (const float*)d_in[7];
    const float* neB2 = (const float*)d_in[8];
    const float* eeW1 = (const float*)d_in[9];
    const float* eeB1 = (const float*)d_in[10];
    const float* eeW2 = (const float*)d_in[11];
    const float* eeB2 = (const float*)d_in[12];
    const float* meW1 = (const float*)d_in[13];  // [5][16][48]
    const float* meB1 = (const float*)d_in[14];
    const float* meW2 = (const float*)d_in[15];  // [5][16][16]
    const float* meB2 = (const float*)d_in[16];
    const float* mnW1 = (const float*)d_in[17];  // [5][16][32]
    const float* mnB1 = (const float*)d_in[18];
    const float* mnW2 = (const float*)d_in[19];
    const float* mnB2 = (const float*)d_in[20];
    const float* dW1  = (const float*)d_in[21];
    const float* dB1  = (const float*)d_in[22];
    const float* dW2  = (const float*)d_in[23];
    const float* dB2  = (const float*)d_in[24];

    const int TB = 256;
    const int gN  = (NN + TB - 1) / TB;
    const int gN2 = (NN / 2 + TB - 1) / TB;
    const int gE  = (NE + TB - 1) / TB;

    k_encode_node<<<gN, TB>>>(nodes, neW1, neB1, neW2, neB2, meW1, meB1);
    k_encode_edge<<<gE, TB>>>(edges, eeW1, eeB1, eeW2, eeB2, receivers);

    for (int r = 0; r < RND; r++) {
        k_edge<<<gE, TB>>>(senders, receivers,
                           meW1 + (size_t)r * 16 * 48,
                           meW2 + (size_t)r * 256,
                           meB2 + (size_t)r * 16,
                           (r == 0) ? bi : nullptr);
        int has_next = (r + 1 < RND) ? 1 : 0;
        const float* nW1 = has_next ? meW1 + (size_t)(r + 1) * 16 * 48 : meW1;
        const float* nB1 = has_next ? meB1 + (size_t)(r + 1) * 16 : meB1;
        k_node_upd<<<gN2, TB>>>(mnW1 + (size_t)r * 512, mnB1 + (size_t)r * 16,
                                mnW2 + (size_t)r * 256, mnB2 + (size_t)r * 16,
                                nW1, nB1, has_next);
    }

    int write_extra = (out_size >= 3 * NE) ? 1 : 0;
    k_dec<<<gE, TB>>>(senders, receivers, bi, dW1, dB1, dW2, dB2,
                      (float*)d_out, write_extra);
}

// round 10
// speedup vs baseline: 1.0987x; 1.0987x over previous
#include <cuda_runtime.h>
#include <cstdint>

#define NN 100000
#define NE 1000000
#define NB 500000
#define H  16
#define RND 5

#define SQ 258   // float4 pitch (258 % 8 == 2 -> conflict-free)

typedef unsigned long long ull;

// ---------------- scratch ---------------------------------------------------
__device__ __align__(16) float g_nf[NN * H];
__device__ __align__(16) float g_ef[NE * H];
__device__ __align__(16) float g_pre_s[NN * H];   // W1[:,0:16]  @ nf
__device__ __align__(16) float g_pre_r[NN * H];   // W1[:,16:32] @ nf + b1
__device__ __align__(16) float g_agg[NN * H];
__device__ float g_deg[NN];
__device__ int   g_win[NE];

// ---------------- helpers ---------------------------------------------------
__device__ __forceinline__ ull pk(float a, float b) {
    ull r; asm("mov.b64 %0,{%1,%2};" : "=l"(r) : "f"(a), "f"(b)); return r;
}
__device__ __forceinline__ float2 upk(ull a) {
    float2 f; asm("mov.b64 {%0,%1},%2;" : "=f"(f.x), "=f"(f.y) : "l"(a)); return f;
}
__device__ __forceinline__ ull fma2(ull a, ull b, ull c) {
    ull d; asm("fma.rn.f32x2 %0,%1,%2,%3;" : "=l"(d) : "l"(a), "l"(b), "l"(c)); return d;
}

__device__ __forceinline__ float4 ldg_cs4(const float4* p) {
    float4 v;
    asm volatile("ld.global.cs.v4.f32 {%0,%1,%2,%3}, [%4];"
                 : "=f"(v.x), "=f"(v.y), "=f"(v.z), "=f"(v.w) : "l"(p));
    return v;
}
__device__ __forceinline__ void stg_cs4(float4* p, float4 v) {
    asm volatile("st.global.cs.v4.f32 [%0], {%1,%2,%3,%4};"
                 :: "l"(p), "f"(v.x), "f"(v.y), "f"(v.z), "f"(v.w) : "memory");
}

__device__ __forceinline__ void ld16(const float* __restrict__ p, float* f) {
    const float4* q = (const float4*)p;
    float4 a = q[0], b = q[1], c = q[2], d = q[3];
    f[0]=a.x; f[1]=a.y; f[2]=a.z; f[3]=a.w;
    f[4]=b.x; f[5]=b.y; f[6]=b.z; f[7]=b.w;
    f[8]=c.x; f[9]=c.y; f[10]=c.z; f[11]=c.w;
    f[12]=d.x; f[13]=d.y; f[14]=d.z; f[15]=d.w;
}
__device__ __forceinline__ void st16(float* __restrict__ p, const float* f) {
    float4* q = (float4*)p;
    q[0] = make_float4(f[0], f[1], f[2], f[3]);
    q[1] = make_float4(f[4], f[5], f[6], f[7]);
    q[2] = make_float4(f[8], f[9], f[10], f[11]);
    q[3] = make_float4(f[12], f[13], f[14], f[15]);
}
__device__ __forceinline__ void red_add4(float* p, float4 v) {
    asm volatile("red.global.add.v4.f32 [%0], {%1,%2,%3,%4};"
                 :: "l"(p), "f"(v.x), "f"(v.y), "f"(v.z), "f"(v.w) : "memory");
}
__device__ __forceinline__ void red_deg(float* p) {
    asm volatile("red.global.add.f32 [%0], %1;" :: "l"(p), "f"(1.0f) : "memory");
}

__device__ __forceinline__ void pack8(const float* f, ull* xp) {
#pragma unroll
    for (int kk = 0; kk < 8; kk++) xp[kk] = pk(f[2*kk], f[2*kk+1]);
}

// single-vector 16-out GEMV, weights from smem as float4 (k-packed)
__device__ __forceinline__ void single16(const float4* __restrict__ w4, const ull* xp,
                                         const float* init, float* o, bool relu) {
#pragma unroll
    for (int oo = 0; oo < 16; oo++) {
        ull a = 0ULL;
#pragma unroll
        for (int q = 0; q < 4; q++) {
            float4 wv = w4[oo*4 + q];
            a = fma2(pk(wv.x, wv.y), xp[2*q],   a);
            a = fma2(pk(wv.z, wv.w), xp[2*q+1], a);
        }
        float2 f = upk(a);
        float v = init[oo] + f.x + f.y;
        o[oo] = relu ? fmaxf(v, 0.0f) : v;
    }
}

// ---------------- kernels ----------------------------------------------------
// node encoder: scalar->h->h, plus round-0 pre_s/pre_r, agg zeroing, deg zeroing
__global__ void k_encode_node(const float* __restrict__ x,
                              const float* __restrict__ W1, const float* __restrict__ b1,
                              const float* __restrict__ W2, const float* __restrict__ b2,
                              const float* __restrict__ mpW1, const float* __restrict__ mpB1) {
    __shared__ __align__(16) ull sW2p[128], sPSp[128], sPRp[128];
    __shared__ float sW1[16], sB1[16], sB2[16], sB1n[16], sZ[16];
    int tid = threadIdx.x;
    if (tid < 128) {
        int oo = tid >> 3, kk = tid & 7;
        sW2p[tid] = pk(W2[oo*16 + 2*kk],        W2[oo*16 + 2*kk + 1]);
        sPSp[tid] = pk(mpW1[oo*48 + 2*kk],      mpW1[oo*48 + 2*kk + 1]);
        sPRp[tid] = pk(mpW1[oo*48 + 16 + 2*kk], mpW1[oo*48 + 16 + 2*kk + 1]);
    }
    if (tid < 16) {
        sW1[tid] = W1[tid]; sB1[tid] = b1[tid]; sB2[tid] = b2[tid];
        sB1n[tid] = mpB1[tid]; sZ[tid] = 0.0f;
    }
    __syncthreads();
    int n = blockIdx.x * blockDim.x + tid;
    if (n >= NN) return;
    g_deg[n] = 0.0f;
    float xv = x[n];
    float h[16];
#pragma unroll
    for (int k = 0; k < 16; k++) h[k] = fmaxf(sW1[k] * xv + sB1[k], 0.0f);
    ull hp[8]; pack8(h, hp);
    float nf[16];
    single16((const float4*)sW2p, hp, sB2, nf, false);
    st16(&g_nf[(size_t)n * 16], nf);
    ull np[8]; pack8(nf, np);
    float ps[16], pr[16];
    single16((const float4*)sPSp, np, sZ,   ps, false);
    single16((const float4*)sPRp, np, sB1n, pr, false);
    st16(&g_pre_s[(size_t)n * 16], ps);
    st16(&g_pre_r[(size_t)n * 16], pr);
    float z[16];
#pragma unroll
    for (int k = 0; k < 16; k++) z[k] = 0.0f;
    st16(&g_agg[(size_t)n * 16], z);
}

// edge encoder: scalar->h->h, degree count, win init
__global__ void __launch_bounds__(256, 4)
k_encode_edge(const float* __restrict__ x,
              const float* __restrict__ W1, const float* __restrict__ b1,
              const float* __restrict__ W2, const float* __restrict__ b2,
              const int* __restrict__ recv) {
    __shared__ __align__(16) ull sW2p[128];
    __shared__ float sW1[16], sB1[16], sB2[16];
    int tid = threadIdx.x;
    if (tid < 128) {
        int oo = tid >> 3, kk = tid & 7;
        sW2p[tid] = pk(W2[oo*16 + 2*kk], W2[oo*16 + 2*kk + 1]);
    }
    if (tid < 16) { sW1[tid] = W1[tid]; sB1[tid] = b1[tid]; sB2[tid] = b2[tid]; }
    __syncthreads();
    int e = blockIdx.x * blockDim.x + tid;
    if (e >= NE) return;
    g_win[e] = -1;
    float xv = x[e];
    float h[16];
#pragma unroll
    for (int k = 0; k < 16; k++) h[k] = fmaxf(sW1[k] * xv + sB1[k], 0.0f);
    ull hp[8]; pack8(h, hp);
    float ef[16];
    single16((const float4*)sW2p, hp, sB2, ef, false);
    st16(&g_ef[(size_t)e * 16], ef);
    red_deg(&g_deg[recv[e]]);
}

// per-round edge update (EXACT R8 structure): 256-edge tile staged through
// smem, paired compute sharing weight LDS, .cs streaming hints on ef.
__global__ void __launch_bounds__(256, 4)
k_edge(const int* __restrict__ snd, const int* __restrict__ rcv,
       const float* __restrict__ W1, const float* __restrict__ W2,
       const float* __restrict__ b2) {
    __shared__ __align__(16) float4 sE[4 * SQ];
    __shared__ __align__(16) float4 sP[4 * SQ];
    __shared__ __align__(16) ull sW1t[128];   // [k][jpair]
    __shared__ __align__(16) ull sW2t[128];   // [g][k][j2]
    __shared__ __align__(16) ull sB2p[8];

    int tid = threadIdx.x;
    int base = blockIdx.x * 256;
    int nE = NE - base; if (nE > 256) nE = 256;

    if (tid < 128) {
        int k = tid >> 3, j = tid & 7;
        sW1t[k * 8 + j] = pk(W1[(2*j)*48 + 32 + k], W1[(2*j+1)*48 + 32 + k]);
        int g = tid >> 5, rem = tid & 31;
        int kk = rem >> 1, j2 = rem & 1;
        sW2t[tid] = pk(W2[(4*g + 2*j2)*16 + kk], W2[(4*g + 2*j2 + 1)*16 + kk]);
    }
    if (tid < 8) sB2p[tid] = pk(b2[2*tid], b2[2*tid+1]);

    const float4* gE = (const float4*)g_ef + (size_t)base * 4;
    const float4* gS = (const float4*)g_pre_s;
    const float4* gR = (const float4*)g_pre_r;
#pragma unroll
    for (int j = 0; j < 4; j++) {
        int g = j * 256 + tid;
        int e = g >> 2, seg = g & 3;
        if (e < nE) {
            sE[seg * SQ + e] = ldg_cs4(gE + g);
            int ns = snd[base + e];
            int nr = rcv[base + e];
            float4 a = gS[(size_t)ns * 4 + seg];
            float4 b = gR[(size_t)nr * 4 + seg];
            sP[seg * SQ + e] = make_float4(a.x + b.x, a.y + b.y, a.z + b.z, a.w + b.w);
        }
    }
    __syncthreads();

    if (tid < 128) {
        int eA = tid, eB = tid + 128;

        ull accA[8], accB[8];
#pragma unroll
        for (int j = 0; j < 8; j++) { accA[j] = 0ULL; accB[j] = 0ULL; }
#pragma unroll
        for (int c = 0; c < 4; c++) {
            float4 xvA = sE[c * SQ + eA];
            float4 xvB = sE[c * SQ + eB];
            const float* xa = (const float*)&xvA;
            const float* xb = (const float*)&xvB;
#pragma unroll
            for (int t = 0; t < 4; t++) {
                int k = 4*c + t;
                ull xxA = pk(xa[t], xa[t]);
                ull xxB = pk(xb[t], xb[t]);
                const ull* wr = &sW1t[k * 8];
#pragma unroll
                for (int j = 0; j < 8; j++) {
                    ull wv = wr[j];
                    accA[j] = fma2(wv, xxA, accA[j]);
                    accB[j] = fma2(wv, xxB, accB[j]);
                }
            }
        }
        float hA[16], hB[16];
#pragma unroll
        for (int c = 0; c < 4; c++) {
            float4 pA = sP[c * SQ + eA];
            float4 pB = sP[c * SQ + eB];
            float2 a0 = upk(accA[2*c]), a1 = upk(accA[2*c+1]);
            float2 b0 = upk(accB[2*c]), b1 = upk(accB[2*c+1]);
            hA[4*c+0] = fmaxf(a0.x + pA.x, 0.0f);
            hA[4*c+1] = fmaxf(a0.y + pA.y, 0.0f);
            hA[4*c+2] = fmaxf(a1.x + pA.z, 0.0f);
            hA[4*c+3] = fmaxf(a1.y + pA.w, 0.0f);
            hB[4*c+0] = fmaxf(b0.x + pB.x, 0.0f);
            hB[4*c+1] = fmaxf(b0.y + pB.y, 0.0f);
            hB[4*c+2] = fmaxf(b1.x + pB.z, 0.0f);
            hB[4*c+3] = fmaxf(b1.y + pB.w, 0.0f);
        }
#pragma unroll
        for (int g = 0; g < 4; g++) {
            ull aA0 = 0ULL, aA1 = 0ULL, aB0 = 0ULL, aB1 = 0ULL;
            const ull* w2 = &sW2t[g * 32];
#pragma unroll
            for (int k = 0; k < 16; k++) {
                ull w0 = w2[2*k], w1 = w2[2*k+1];
                ull xxA = pk(hA[k], hA[k]);
                ull xxB = pk(hB[k], hB[k]);
                aA0 = fma2(w0, xxA, aA0); aA1 = fma2(w1, xxA, aA1);
                aB0 = fma2(w0, xxB, aB0); aB1 = fma2(w1, xxB, aB1);
            }
            float2 f0 = upk(aA0), f1 = upk(aA1);
            float2 g0 = upk(aB0), g1 = upk(aB1);
            float2 c0 = upk(sB2p[2*g]), c1 = upk(sB2p[2*g+1]);
            sE[g * SQ + eA] = make_float4(f0.x + c0.x, f0.y + c0.y, f1.x + c1.x, f1.y + c1.y);
            sE[g * SQ + eB] = make_float4(g0.x + c0.x, g0.y + c0.y, g1.x + c1.x, g1.y + c1.y);
        }
    }
    __syncthreads();

    float4* gEo = (float4*)g_ef + (size_t)base * 4;
#pragma unroll
    for (int j = 0; j < 4; j++) {
        int g = j * 256 + tid;
        int e = g >> 2, seg = g & 3;
        if (e < nE) {
            float4 v = sE[seg * SQ + e];
            stg_cs4(gEo + g, v);
            int nr = rcv[base + e];
            red_add4(&g_agg[(size_t)nr * 16 + seg * 4], v);
        }
    }
}

// per-round node update: ONE node per thread, streaming out-packed compute
// (low registers -> 4 CTAs/SM, grid 391). Also computes pre for next round.
// Weight layouts transposed [k][output-pair j].
__global__ void __launch_bounds__(256, 4)
k_node_upd(const float* __restrict__ W1, const float* __restrict__ b1,
           const float* __restrict__ W2, const float* __restrict__ b2,
           const float* __restrict__ nW1, const float* __restrict__ nB1,
           int has_next) {
    __shared__ __align__(16) ull sW1t[256];   // k 0..31
    __shared__ __align__(16) ull sW2t[128];   // k 0..15
    __shared__ __align__(16) ull sPSt[128], sPRt[128];
    __shared__ __align__(16) ull sB1p[8], sB2p[8], sB1np[8];
    int tid = threadIdx.x;
    {
        int k = tid >> 3, j = tid & 7;   // k 0..31
        sW1t[tid] = pk(W1[(2*j)*32 + k], W1[(2*j+1)*32 + k]);
    }
    if (tid < 128) {
        int k = tid >> 3, j = tid & 7;   // k 0..15
        sW2t[tid] = pk(W2[(2*j)*16 + k], W2[(2*j+1)*16 + k]);
        if (has_next) {
            sPSt[tid] = pk(nW1[(2*j)*48 + k],      nW1[(2*j+1)*48 + k]);
            sPRt[tid] = pk(nW1[(2*j)*48 + 16 + k], nW1[(2*j+1)*48 + 16 + k]);
        }
    }
    if (tid < 8) {
        sB1p[tid] = pk(b1[2*tid], b1[2*tid+1]);
        sB2p[tid] = pk(b2[2*tid], b2[2*tid+1]);
        sB1np[tid] = has_next ? pk(nB1[2*tid], nB1[2*tid+1]) : 0ULL;
    }
    __syncthreads();
    int n = blockIdx.x * blockDim.x + tid;
    if (n >= NN) return;

    float f[16], a[16];
    ld16(&g_nf[(size_t)n * 16], f);
    ld16(&g_agg[(size_t)n * 16], a);
    float inv = 1.0f / fmaxf(g_deg[n], 1.0f);
#pragma unroll
    for (int k = 0; k < 16; k++) a[k] *= inv;

    // layer 1: 32 inputs -> 16 outs (8 f32x2 accumulators)
    ull acc[8];
#pragma unroll
    for (int j = 0; j < 8; j++) acc[j] = 0ULL;
#pragma unroll
    for (int k = 0; k < 16; k++) {
        ull xx = pk(f[k], f[k]);
        const ull* wr = &sW1t[k * 8];
#pragma unroll
        for (int j = 0; j < 8; j++) acc[j] = fma2(wr[j], xx, acc[j]);
    }
#pragma unroll
    for (int k = 0; k < 16; k++) {
        ull xx = pk(a[k], a[k]);
        const ull* wr = &sW1t[(16 + k) * 8];
#pragma unroll
        for (int j = 0; j < 8; j++) acc[j] = fma2(wr[j], xx, acc[j]);
    }
    float h[16];
#pragma unroll
    for (int j = 0; j < 8; j++) {
        float2 v = upk(acc[j]);
        float2 b = upk(sB1p[j]);
        h[2*j]   = fmaxf(v.x + b.x, 0.0f);
        h[2*j+1] = fmaxf(v.y + b.y, 0.0f);
    }

    // layer 2
    ull acc2[8];
#pragma unroll
    for (int j = 0; j < 8; j++) acc2[j] = 0ULL;
#pragma unroll
    for (int k = 0; k < 16; k++) {
        ull xx = pk(h[k], h[k]);
        const ull* wr = &sW2t[k * 8];
#pragma unroll
        for (int j = 0; j < 8; j++) acc2[j] = fma2(wr[j], xx, acc2[j]);
    }
    float o[16];
#pragma unroll
    for (int j = 0; j < 8; j++) {
        float2 v = upk(acc2[j]);
        float2 b = upk(sB2p[j]);
        o[2*j]   = v.x + b.x;
        o[2*j+1] = v.y + b.y;
    }
    st16(&g_nf[(size_t)n * 16], o);

    if (has_next) {
        // pre_s
        ull accS[8];
#pragma unroll
        for (int j = 0; j < 8; j++) accS[j] = 0ULL;
#pragma unroll
        for (int k = 0; k < 16; k++) {
            ull xx = pk(o[k], o[k]);
            const ull* wr = &sPSt[k * 8];
#pragma unroll
            for (int j = 0; j < 8; j++) accS[j] = fma2(wr[j], xx, accS[j]);
        }
        float ps[16];
#pragma unroll
        for (int j = 0; j < 8; j++) {
            float2 v = upk(accS[j]);
            ps[2*j] = v.x; ps[2*j+1] = v.y;
        }
        st16(&g_pre_s[(size_t)n * 16], ps);
        // pre_r (+ next round's b1)
        ull accR[8];
#pragma unroll
        for (int j = 0; j < 8; j++) accR[j] = 0ULL;
#pragma unroll
        for (int k = 0; k < 16; k++) {
            ull xx = pk(o[k], o[k]);
            const ull* wr = &sPRt[k * 8];
#pragma unroll
            for (int j = 0; j < 8; j++) accR[j] = fma2(wr[j], xx, accR[j]);
        }
        float pr[16];
#pragma unroll
        for (int j = 0; j < 8; j++) {
            float2 v = upk(accR[j]);
            float2 b = upk(sB1np[j]);
            pr[2*j] = v.x + b.x; pr[2*j+1] = v.y + b.y;
        }
        st16(&g_pre_r[(size_t)n * 16], pr);
        float z[16];
#pragma unroll
        for (int k = 0; k < 16; k++) z[k] = 0.0f;
        st16(&g_agg[(size_t)n * 16], z);
    }
}

// bi-edge averaging winner election (sequential last-write-wins semantics)
__global__ void k_bi(const int* __restrict__ bi) {
    int p = blockIdx.x * blockDim.x + threadIdx.x;
    if (p >= NB) return;
    atomicMax(&g_win[bi[p]], p);
    atomicMax(&g_win[bi[NB + p]], (1 << 30) | p);
}

// decode: bi-average from pre-decode ef, MLP h->h->1, tril mask
__global__ void __launch_bounds__(256, 4)
k_dec(const int* __restrict__ snd, const int* __restrict__ rcv,
      const int* __restrict__ bi,
      const float* __restrict__ W1, const float* __restrict__ b1,
      const float* __restrict__ W2, const float* __restrict__ b2,
      float* __restrict__ out, int write_extra) {
    __shared__ __align__(16) ull sW1p[128];
    __shared__ float sB1[16], sW2[16], sB2;
    int tid = threadIdx.x;
    if (tid < 128) {
        int oo = tid >> 3, kk = tid & 7;
        sW1p[tid] = pk(W1[oo*16 + 2*kk], W1[oo*16 + 2*kk + 1]);
    }
    if (tid < 16) { sB1[tid] = b1[tid]; sW2[tid] = W2[tid]; }
    if (tid == 0) sB2 = b2[0];
    __syncthreads();
    int e = blockIdx.x * blockDim.x + tid;
    if (e >= NE) return;
    float f[16];
    int w = g_win[e];
    if (w >= 0) {
        int p = w & 0x3FFFFFFF;
        int i = bi[p], j = bi[NB + p];
        float fi[16], fj[16];
        ld16(&g_ef[(size_t)i * 16], fi);
        ld16(&g_ef[(size_t)j * 16], fj);
#pragma unroll
        for (int k = 0; k < 16; k++) f[k] = 0.5f * (fi[k] + fj[k]);
    } else {
        ld16(&g_ef[(size_t)e * 16], f);
    }
    ull fp[8]; pack8(f, fp);
    float h[16];
    single16((const float4*)sW1p, fp, sB1, h, true);
    float val = sB2;
#pragma unroll
    for (int o = 0; o < 16; o++) val += sW2[o] * h[o];
    int s = snd[e], r = rcv[e];
    out[e] = (r >= s) ? val : 0.0f;
    if (write_extra) {
        out[NE + e] = (float)r;
        out[2 * NE + e] = (float)s;
    }
}

// ---------------- launch -----------------------------------------------------
extern "C" void kernel_launch(void* const* d_in, const int* in_sizes, int n_in,
                              void* d_out, int out_size) {
    const float* nodes    = (const float*)d_in[0];
    const float* edges    = (const float*)d_in[1];
    const int*   receivers= (const int*)d_in[2];
    const int*   senders  = (const int*)d_in[3];
    const int*   bi       = (const int*)d_in[4];
    const float* neW1 = (const float*)d_in[5];
    const float* neB1 = (const float*)d_in[6];
    const float* neW2 = (const float*)d_in[7];
    const float* neB2 = (const float*)d_in[8];
    const float* eeW1 = (const float*)d_in[9];
    const float* eeB1 = (const float*)d_in[10];
    const float* eeW2 = (const float*)d_in[11];
    const float* eeB2 = (const float*)d_in[12];
    const float* meW1 = (const float*)d_in[13];  // [5][16][48]
    const float* meB1 = (const float*)d_in[14];
    const float* meW2 = (const float*)d_in[15];  // [5][16][16]
    const float* meB2 = (const float*)d_in[16];
    const float* mnW1 = (const float*)d_in[17];  // [5][16][32]
    const float* mnB1 = (const float*)d_in[18];
    const float* mnW2 = (const float*)d_in[19];
    const float* mnB2 = (const float*)d_in[20];
    const float* dW1  = (const float*)d_in[21];
    const float* dB1  = (const float*)d_in[22];
    const float* dW2  = (const float*)d_in[23];
    const float* dB2  = (const float*)d_in[24];

    const int TB = 256;
    const int gN  = (NN + TB - 1) / TB;
    const int gE  = (NE + TB - 1) / TB;
    const int gB  = (NB + TB - 1) / TB;

    k_encode_node<<<gN, TB>>>(nodes, neW1, neB1, neW2, neB2, meW1, meB1);
    k_encode_edge<<<gE, TB>>>(edges, eeW1, eeB1, eeW2, eeB2, receivers);
    k_bi<<<gB, TB>>>(bi);   // independent of rounds; off the critical tail

    for (int r = 0; r < RND; r++) {
        k_edge<<<gE, TB>>>(senders, receivers,
                           meW1 + (size_t)r * 16 * 48,
                           meW2 + (size_t)r * 256,
                           meB2 + (size_t)r * 16);
        int has_next = (r + 1 < RND) ? 1 : 0;
        const float* nW1 = has_next ? meW1 + (size_t)(r + 1) * 16 * 48 : meW1;
        const float* nB1 = has_next ? meB1 + (size_t)(r + 1) * 16 : meB1;
        k_node_upd<<<gN, TB>>>(mnW1 + (size_t)r * 512, mnB1 + (size_t)r * 16,
                               mnW2 + (size_t)r * 256, mnB2 + (size_t)r * 16,
                               nW1, nB1, has_next);
    }

    int write_extra = (out_size >= 3 * NE) ? 1 : 0;
    k_dec<<<gE, TB>>>(senders, receivers, bi, dW1, dB1, dW2, dB2,
                      (float*)d_out, write_extra);
}

// round 11
// speedup vs baseline: 1.1161x; 1.0158x over previous
#include <cuda_runtime.h>
#include <cstdint>

#define NN 100000
#define NE 1000000
#define NB 500000
#define H  16
#define RND 5

#define SQ 258   // float4 pitch (258 % 8 == 2 -> conflict-free)

typedef unsigned long long ull;

// ---------------- scratch ---------------------------------------------------
__device__ __align__(16) float g_nf[NN * H];
__device__ __align__(16) float g_ef[NE * H];
__device__ __align__(16) float g_pre_s[NN * H];   // W1[:,0:16]  @ nf
__device__ __align__(16) float g_pre_r[NN * H];   // W1[:,16:32] @ nf + b1
__device__ __align__(16) float g_agg[NN * H];
__device__ float g_deg[NN];
__device__ int   g_win[NE];

// ---------------- helpers ---------------------------------------------------
__device__ __forceinline__ ull pk(float a, float b) {
    ull r; asm("mov.b64 %0,{%1,%2};" : "=l"(r) : "f"(a), "f"(b)); return r;
}
__device__ __forceinline__ float2 upk(ull a) {
    float2 f; asm("mov.b64 {%0,%1},%2;" : "=f"(f.x), "=f"(f.y) : "l"(a)); return f;
}
__device__ __forceinline__ ull fma2(ull a, ull b, ull c) {
    ull d; asm("fma.rn.f32x2 %0,%1,%2,%3;" : "=l"(d) : "l"(a), "l"(b), "l"(c)); return d;
}

__device__ __forceinline__ float4 ldg_cs4(const float4* p) {
    float4 v;
    asm volatile("ld.global.cs.v4.f32 {%0,%1,%2,%3}, [%4];"
                 : "=f"(v.x), "=f"(v.y), "=f"(v.z), "=f"(v.w) : "l"(p));
    return v;
}
__device__ __forceinline__ void stg_cs4(float4* p, float4 v) {
    asm volatile("st.global.cs.v4.f32 [%0], {%1,%2,%3,%4};"
                 :: "l"(p), "f"(v.x), "f"(v.y), "f"(v.z), "f"(v.w) : "memory");
}

__device__ __forceinline__ void ld16(const float* __restrict__ p, float* f) {
    const float4* q = (const float4*)p;
    float4 a = q[0], b = q[1], c = q[2], d = q[3];
    f[0]=a.x; f[1]=a.y; f[2]=a.z; f[3]=a.w;
    f[4]=b.x; f[5]=b.y; f[6]=b.z; f[7]=b.w;
    f[8]=c.x; f[9]=c.y; f[10]=c.z; f[11]=c.w;
    f[12]=d.x; f[13]=d.y; f[14]=d.z; f[15]=d.w;
}
__device__ __forceinline__ void st16(float* __restrict__ p, const float* f) {
    float4* q = (float4*)p;
    q[0] = make_float4(f[0], f[1], f[2], f[3]);
    q[1] = make_float4(f[4], f[5], f[6], f[7]);
    q[2] = make_float4(f[8], f[9], f[10], f[11]);
    q[3] = make_float4(f[12], f[13], f[14], f[15]);
}
__device__ __forceinline__ void red_add4(float* p, float4 v) {
    asm volatile("red.global.add.v4.f32 [%0], {%1,%2,%3,%4};"
                 :: "l"(p), "f"(v.x), "f"(v.y), "f"(v.z), "f"(v.w) : "memory");
}
__device__ __forceinline__ void red_deg(float* p) {
    asm volatile("red.global.add.f32 [%0], %1;" :: "l"(p), "f"(1.0f) : "memory");
}

__device__ __forceinline__ void pack8(const float* f, ull* xp) {
#pragma unroll
    for (int kk = 0; kk < 8; kk++) xp[kk] = pk(f[2*kk], f[2*kk+1]);
}

// single-vector 16-out GEMV, weights from smem as float4 (k-packed)
__device__ __forceinline__ void single16(const float4* __restrict__ w4, const ull* xp,
                                         const float* init, float* o, bool relu) {
#pragma unroll
    for (int oo = 0; oo < 16; oo++) {
        ull a = 0ULL;
#pragma unroll
        for (int q = 0; q < 4; q++) {
            float4 wv = w4[oo*4 + q];
            a = fma2(pk(wv.x, wv.y), xp[2*q],   a);
            a = fma2(pk(wv.z, wv.w), xp[2*q+1], a);
        }
        float2 f = upk(a);
        float v = init[oo] + f.x + f.y;
        o[oo] = relu ? fmaxf(v, 0.0f) : v;
    }
}

// ---------------- kernels ----------------------------------------------------
// node encoder: scalar->h->h, plus round-0 pre_s/pre_r, agg zeroing, deg zeroing
__global__ void k_encode_node(const float* __restrict__ x,
                              const float* __restrict__ W1, const float* __restrict__ b1,
                              const float* __restrict__ W2, const float* __restrict__ b2,
                              const float* __restrict__ mpW1, const float* __restrict__ mpB1) {
    __shared__ __align__(16) ull sW2p[128], sPSp[128], sPRp[128];
    __shared__ float sW1[16], sB1[16], sB2[16], sB1n[16], sZ[16];
    int tid = threadIdx.x;
    if (tid < 128) {
        int oo = tid >> 3, kk = tid & 7;
        sW2p[tid] = pk(W2[oo*16 + 2*kk],        W2[oo*16 + 2*kk + 1]);
        sPSp[tid] = pk(mpW1[oo*48 + 2*kk],      mpW1[oo*48 + 2*kk + 1]);
        sPRp[tid] = pk(mpW1[oo*48 + 16 + 2*kk], mpW1[oo*48 + 16 + 2*kk + 1]);
    }
    if (tid < 16) {
        sW1[tid] = W1[tid]; sB1[tid] = b1[tid]; sB2[tid] = b2[tid];
        sB1n[tid] = mpB1[tid]; sZ[tid] = 0.0f;
    }
    __syncthreads();
    int n = blockIdx.x * blockDim.x + tid;
    if (n >= NN) return;
    g_deg[n] = 0.0f;
    float xv = x[n];
    float h[16];
#pragma unroll
    for (int k = 0; k < 16; k++) h[k] = fmaxf(sW1[k] * xv + sB1[k], 0.0f);
    ull hp[8]; pack8(h, hp);
    float nf[16];
    single16((const float4*)sW2p, hp, sB2, nf, false);
    st16(&g_nf[(size_t)n * 16], nf);
    ull np[8]; pack8(nf, np);
    float ps[16], pr[16];
    single16((const float4*)sPSp, np, sZ,   ps, false);
    single16((const float4*)sPRp, np, sB1n, pr, false);
    st16(&g_pre_s[(size_t)n * 16], ps);
    st16(&g_pre_r[(size_t)n * 16], pr);
    float z[16];
#pragma unroll
    for (int k = 0; k < 16; k++) z[k] = 0.0f;
    st16(&g_agg[(size_t)n * 16], z);
}

// edge encoder: scalar->h->h, degree count, win init
__global__ void __launch_bounds__(256, 4)
k_encode_edge(const float* __restrict__ x,
              const float* __restrict__ W1, const float* __restrict__ b1,
              const float* __restrict__ W2, const float* __restrict__ b2,
              const int* __restrict__ recv) {
    __shared__ __align__(16) ull sW2p[128];
    __shared__ float sW1[16], sB1[16], sB2[16];
    int tid = threadIdx.x;
    if (tid < 128) {
        int oo = tid >> 3, kk = tid & 7;
        sW2p[tid] = pk(W2[oo*16 + 2*kk], W2[oo*16 + 2*kk + 1]);
    }
    if (tid < 16) { sW1[tid] = W1[tid]; sB1[tid] = b1[tid]; sB2[tid] = b2[tid]; }
    __syncthreads();
    int e = blockIdx.x * blockDim.x + tid;
    if (e >= NE) return;
    g_win[e] = -1;
    float xv = x[e];
    float h[16];
#pragma unroll
    for (int k = 0; k < 16; k++) h[k] = fmaxf(sW1[k] * xv + sB1[k], 0.0f);
    ull hp[8]; pack8(h, hp);
    float ef[16];
    single16((const float4*)sW2p, hp, sB2, ef, false);
    st16(&g_ef[(size_t)e * 16], ef);
    red_deg(&g_deg[recv[e]]);
}

// per-round edge update (R8 structure): 256-edge tile staged through smem,
// paired compute sharing weight LDS, .cs streaming hints on ef.
// do_scatter=0 for the FINAL round: agg is never consumed afterwards, so
// the REDG scatter (and its rcv reload) is skipped entirely.
__global__ void __launch_bounds__(256, 4)
k_edge(const int* __restrict__ snd, const int* __restrict__ rcv,
       const float* __restrict__ W1, const float* __restrict__ W2,
       const float* __restrict__ b2, int do_scatter) {
    __shared__ __align__(16) float4 sE[4 * SQ];
    __shared__ __align__(16) float4 sP[4 * SQ];
    __shared__ __align__(16) ull sW1t[128];   // [k][jpair]
    __shared__ __align__(16) ull sW2t[128];   // [g][k][j2]
    __shared__ __align__(16) ull sB2p[8];

    int tid = threadIdx.x;
    int base = blockIdx.x * 256;
    int nE = NE - base; if (nE > 256) nE = 256;

    if (tid < 128) {
        int k = tid >> 3, j = tid & 7;
        sW1t[k * 8 + j] = pk(W1[(2*j)*48 + 32 + k], W1[(2*j+1)*48 + 32 + k]);
        int g = tid >> 5, rem = tid & 31;
        int kk = rem >> 1, j2 = rem & 1;
        sW2t[tid] = pk(W2[(4*g + 2*j2)*16 + kk], W2[(4*g + 2*j2 + 1)*16 + kk]);
    }
    if (tid < 8) sB2p[tid] = pk(b2[2*tid], b2[2*tid+1]);

    const float4* gE = (const float4*)g_ef + (size_t)base * 4;
    const float4* gS = (const float4*)g_pre_s;
    const float4* gR = (const float4*)g_pre_r;
#pragma unroll
    for (int j = 0; j < 4; j++) {
        int g = j * 256 + tid;
        int e = g >> 2, seg = g & 3;
        if (e < nE) {
            sE[seg * SQ + e] = ldg_cs4(gE + g);
            int ns = snd[base + e];
            int nr = rcv[base + e];
            float4 a = gS[(size_t)ns * 4 + seg];
            float4 b = gR[(size_t)nr * 4 + seg];
            sP[seg * SQ + e] = make_float4(a.x + b.x, a.y + b.y, a.z + b.z, a.w + b.w);
        }
    }
    __syncthreads();

    if (tid < 128) {
        int eA = tid, eB = tid + 128;

        ull accA[8], accB[8];
#pragma unroll
        for (int j = 0; j < 8; j++) { accA[j] = 0ULL; accB[j] = 0ULL; }
#pragma unroll
        for (int c = 0; c < 4; c++) {
            float4 xvA = sE[c * SQ + eA];
            float4 xvB = sE[c * SQ + eB];
            const float* xa = (const float*)&xvA;
            const float* xb = (const float*)&xvB;
#pragma unroll
            for (int t = 0; t < 4; t++) {
                int k = 4*c + t;
                ull xxA = pk(xa[t], xa[t]);
                ull xxB = pk(xb[t], xb[t]);
                const ull* wr = &sW1t[k * 8];
#pragma unroll
                for (int j = 0; j < 8; j++) {
                    ull wv = wr[j];
                    accA[j] = fma2(wv, xxA, accA[j]);
                    accB[j] = fma2(wv, xxB, accB[j]);
                }
            }
        }
        float hA[16], hB[16];
#pragma unroll
        for (int c = 0; c < 4; c++) {
            float4 pA = sP[c * SQ + eA];
            float4 pB = sP[c * SQ + eB];
            float2 a0 = upk(accA[2*c]), a1 = upk(accA[2*c+1]);
            float2 b0 = upk(accB[2*c]), b1 = upk(accB[2*c+1]);
            hA[4*c+0] = fmaxf(a0.x + pA.x, 0.0f);
            hA[4*c+1] = fmaxf(a0.y + pA.y, 0.0f);
            hA[4*c+2] = fmaxf(a1.x + pA.z, 0.0f);
            hA[4*c+3] = fmaxf(a1.y + pA.w, 0.0f);
            hB[4*c+0] = fmaxf(b0.x + pB.x, 0.0f);
            hB[4*c+1] = fmaxf(b0.y + pB.y, 0.0f);
            hB[4*c+2] = fmaxf(b1.x + pB.z, 0.0f);
            hB[4*c+3] = fmaxf(b1.y + pB.w, 0.0f);
        }
#pragma unroll
        for (int g = 0; g < 4; g++) {
            ull aA0 = 0ULL, aA1 = 0ULL, aB0 = 0ULL, aB1 = 0ULL;
            const ull* w2 = &sW2t[g * 32];
#pragma unroll
            for (int k = 0; k < 16; k++) {
                ull w0 = w2[2*k], w1 = w2[2*k+1];
                ull xxA = pk(hA[k], hA[k]);
                ull xxB = pk(hB[k], hB[k]);
                aA0 = fma2(w0, xxA, aA0); aA1 = fma2(w1, xxA, aA1);
                aB0 = fma2(w0, xxB, aB0); aB1 = fma2(w1, xxB, aB1);
            }
            float2 f0 = upk(aA0), f1 = upk(aA1);
            float2 g0 = upk(aB0), g1 = upk(aB1);
            float2 c0 = upk(sB2p[2*g]), c1 = upk(sB2p[2*g+1]);
            sE[g * SQ + eA] = make_float4(f0.x + c0.x, f0.y + c0.y, f1.x + c1.x, f1.y + c1.y);
            sE[g * SQ + eB] = make_float4(g0.x + c0.x, g0.y + c0.y, g1.x + c1.x, g1.y + c1.y);
        }
    }
    __syncthreads();

    float4* gEo = (float4*)g_ef + (size_t)base * 4;
    if (do_scatter) {
#pragma unroll
        for (int j = 0; j < 4; j++) {
            int g = j * 256 + tid;
            int e = g >> 2, seg = g & 3;
            if (e < nE) {
                float4 v = sE[seg * SQ + e];
                stg_cs4(gEo + g, v);
                int nr = rcv[base + e];
                red_add4(&g_agg[(size_t)nr * 16 + seg * 4], v);
            }
        }
    } else {
#pragma unroll
        for (int j = 0; j < 4; j++) {
            int g = j * 256 + tid;
            int e = g >> 2;
            if (e < nE) stg_cs4(gEo + g, sE[(g & 3) * SQ + e]);
        }
    }
}

// per-round node update: ONE node per thread, streaming out-packed compute.
// Also computes pre_s/pre_r for the next round and re-zeroes agg.
__global__ void __launch_bounds__(256, 4)
k_node_upd(const float* __restrict__ W1, const float* __restrict__ b1,
           const float* __restrict__ W2, const float* __restrict__ b2,
           const float* __restrict__ nW1, const float* __restrict__ nB1) {
    __shared__ __align__(16) ull sW1t[256];   // k 0..31
    __shared__ __align__(16) ull sW2t[128];   // k 0..15
    __shared__ __align__(16) ull sPSt[128], sPRt[128];
    __shared__ __align__(16) ull sB1p[8], sB2p[8], sB1np[8];
    int tid = threadIdx.x;
    {
        int k = tid >> 3, j = tid & 7;   // k 0..31
        sW1t[tid] = pk(W1[(2*j)*32 + k], W1[(2*j+1)*32 + k]);
    }
    if (tid < 128) {
        int k = tid >> 3, j = tid & 7;   // k 0..15
        sW2t[tid] = pk(W2[(2*j)*16 + k], W2[(2*j+1)*16 + k]);
        sPSt[tid] = pk(nW1[(2*j)*48 + k],      nW1[(2*j+1)*48 + k]);
        sPRt[tid] = pk(nW1[(2*j)*48 + 16 + k], nW1[(2*j+1)*48 + 16 + k]);
    }
    if (tid < 8) {
        sB1p[tid]  = pk(b1[2*tid], b1[2*tid+1]);
        sB2p[tid]  = pk(b2[2*tid], b2[2*tid+1]);
        sB1np[tid] = pk(nB1[2*tid], nB1[2*tid+1]);
    }
    __syncthreads();
    int n = blockIdx.x * blockDim.x + tid;
    if (n >= NN) return;

    float f[16], a[16];
    ld16(&g_nf[(size_t)n * 16], f);
    ld16(&g_agg[(size_t)n * 16], a);
    float inv = 1.0f / fmaxf(g_deg[n], 1.0f);
#pragma unroll
    for (int k = 0; k < 16; k++) a[k] *= inv;

    // layer 1: 32 inputs -> 16 outs (8 f32x2 accumulators)
    ull acc[8];
#pragma unroll
    for (int j = 0; j < 8; j++) acc[j] = 0ULL;
#pragma unroll
    for (int k = 0; k < 16; k++) {
        ull xx = pk(f[k], f[k]);
        const ull* wr = &sW1t[k * 8];
#pragma unroll
        for (int j = 0; j < 8; j++) acc[j] = fma2(wr[j], xx, acc[j]);
    }
#pragma unroll
    for (int k = 0; k < 16; k++) {
        ull xx = pk(a[k], a[k]);
        const ull* wr = &sW1t[(16 + k) * 8];
#pragma unroll
        for (int j = 0; j < 8; j++) acc[j] = fma2(wr[j], xx, acc[j]);
    }
    float h[16];
#pragma unroll
    for (int j = 0; j < 8; j++) {
        float2 v = upk(acc[j]);
        float2 b = upk(sB1p[j]);
        h[2*j]   = fmaxf(v.x + b.x, 0.0f);
        h[2*j+1] = fmaxf(v.y + b.y, 0.0f);
    }

    // layer 2
    ull acc2[8];
#pragma unroll
    for (int j = 0; j < 8; j++) acc2[j] = 0ULL;
#pragma unroll
    for (int k = 0; k < 16; k++) {
        ull xx = pk(h[k], h[k]);
        const ull* wr = &sW2t[k * 8];
#pragma unroll
        for (int j = 0; j < 8; j++) acc2[j] = fma2(wr[j], xx, acc2[j]);
    }
    float o[16];
#pragma unroll
    for (int j = 0; j < 8; j++) {
        float2 v = upk(acc2[j]);
        float2 b = upk(sB2p[j]);
        o[2*j]   = v.x + b.x;
        o[2*j+1] = v.y + b.y;
    }
    st16(&g_nf[(size_t)n * 16], o);

    // pre_s for next round
    ull accS[8];
#pragma unroll
    for (int j = 0; j < 8; j++) accS[j] = 0ULL;
#pragma unroll
    for (int k = 0; k < 16; k++) {
        ull xx = pk(o[k], o[k]);
        const ull* wr = &sPSt[k * 8];
#pragma unroll
        for (int j = 0; j < 8; j++) accS[j] = fma2(wr[j], xx, accS[j]);
    }
    float ps[16];
#pragma unroll
    for (int j = 0; j < 8; j++) {
        float2 v = upk(accS[j]);
        ps[2*j] = v.x; ps[2*j+1] = v.y;
    }
    st16(&g_pre_s[(size_t)n * 16], ps);
    // pre_r (+ next round's b1)
    ull accR[8];
#pragma unroll
    for (int j = 0; j < 8; j++) accR[j] = 0ULL;
#pragma unroll
    for (int k = 0; k < 16; k++) {
        ull xx = pk(o[k], o[k]);
        const ull* wr = &sPRt[k * 8];
#pragma unroll
        for (int j = 0; j < 8; j++) accR[j] = fma2(wr[j], xx, accR[j]);
    }
    float pr[16];
#pragma unroll
    for (int j = 0; j < 8; j++) {
        float2 v = upk(accR[j]);
        float2 b = upk(sB1np[j]);
        pr[2*j] = v.x + b.x; pr[2*j+1] = v.y + b.y;
    }
    st16(&g_pre_r[(size_t)n * 16], pr);
    float z[16];
#pragma unroll
    for (int k = 0; k < 16; k++) z[k] = 0.0f;
    st16(&g_agg[(size_t)n * 16], z);
}

// bi-edge averaging winner election (sequential last-write-wins semantics)
__global__ void k_bi(const int* __restrict__ bi) {
    int p = blockIdx.x * blockDim.x + threadIdx.x;
    if (p >= NB) return;
    atomicMax(&g_win[bi[p]], p);
    atomicMax(&g_win[bi[NB + p]], (1 << 30) | p);
}

// decode: bi-average from pre-decode ef, MLP h->h->1, tril mask
__global__ void __launch_bounds__(256, 4)
k_dec(const int* __restrict__ snd, const int* __restrict__ rcv,
      const int* __restrict__ bi,
      const float* __restrict__ W1, const float* __restrict__ b1,
      const float* __restrict__ W2, const float* __restrict__ b2,
      float* __restrict__ out, int write_extra) {
    __shared__ __align__(16) ull sW1p[128];
    __shared__ float sB1[16], sW2[16], sB2;
    int tid = threadIdx.x;
    if (tid < 128) {
        int oo = tid >> 3, kk = tid & 7;
        sW1p[tid] = pk(W1[oo*16 + 2*kk], W1[oo*16 + 2*kk + 1]);
    }
    if (tid < 16) { sB1[tid] = b1[tid]; sW2[tid] = W2[tid]; }
    if (tid == 0) sB2 = b2[0];
    __syncthreads();
    int e = blockIdx.x * blockDim.x + tid;
    if (e >= NE) return;
    float f[16];
    int w = g_win[e];
    if (w >= 0) {
        int p = w & 0x3FFFFFFF;
        int i = bi[p], j = bi[NB + p];
        float fi[16], fj[16];
        ld16(&g_ef[(size_t)i * 16], fi);
        ld16(&g_ef[(size_t)j * 16], fj);
#pragma unroll
        for (int k = 0; k < 16; k++) f[k] = 0.5f * (fi[k] + fj[k]);
    } else {
        ld16(&g_ef[(size_t)e * 16], f);
    }
    ull fp[8]; pack8(f, fp);
    float h[16];
    single16((const float4*)sW1p, fp, sB1, h, true);
    float val = sB2;
#pragma unroll
    for (int o = 0; o < 16; o++) val += sW2[o] * h[o];
    int s = snd[e], r = rcv[e];
    out[e] = (r >= s) ? val : 0.0f;
    if (write_extra) {
        out[NE + e] = (float)r;
        out[2 * NE + e] = (float)s;
    }
}

// ---------------- launch -----------------------------------------------------
extern "C" void kernel_launch(void* const* d_in, const int* in_sizes, int n_in,
                              void* d_out, int out_size) {
    const float* nodes    = (const float*)d_in[0];
    const float* edges    = (const float*)d_in[1];
    const int*   receivers= (const int*)d_in[2];
    const int*   senders  = (const int*)d_in[3];
    const int*   bi       = (const int*)d_in[4];
    const float* neW1 = (const float*)d_in[5];
    const float* neB1 = (const float*)d_in[6];
    const float* neW2 = (const float*)d_in[7];
    const float* neB2 = (const float*)d_in[8];
    const float* eeW1 = (const float*)d_in[9];
    const float* eeB1 = (const float*)d_in[10];
    const float* eeW2 = (const float*)d_in[11];
    const float* eeB2 = (const float*)d_in[12];
    const float* meW1 = (const float*)d_in[13];  // [5][16][48]
    const float* meB1 = (const float*)d_in[14];
    const float* meW2 = (const float*)d_in[15];  // [5][16][16]
    const float* meB2 = (const float*)d_in[16];
    const float* mnW1 = (const float*)d_in[17];  // [5][16][32]
    const float* mnB1 = (const float*)d_in[18];
    const float* mnW2 = (const float*)d_in[19];
    const float* mnB2 = (const float*)d_in[20];
    const float* dW1  = (const float*)d_in[21];
    const float* dB1  = (const float*)d_in[22];
    const float* dW2  = (const float*)d_in[23];
    const float* dB2  = (const float*)d_in[24];

    const int TB = 256;
    const int gN  = (NN + TB - 1) / TB;
    const int gE  = (NE + TB - 1) / TB;
    const int gB  = (NB + TB - 1) / TB;

    k_encode_node<<<gN, TB>>>(nodes, neW1, neB1, neW2, neB2, meW1, meB1);
    k_encode_edge<<<gE, TB>>>(edges, eeW1, eeB1, eeW2, eeB2, receivers);
    k_bi<<<gB, TB>>>(bi);   // independent of rounds; off the critical tail

    for (int r = 0; r < RND; r++) {
        int last = (r == RND - 1);
        k_edge<<<gE, TB>>>(senders, receivers,
                           meW1 + (size_t)r * 16 * 48,
                           meW2 + (size_t)r * 256,
                           meB2 + (size_t)r * 16,
                           last ? 0 : 1);
        if (!last) {
            // node update feeds round r+1 (the final round's node update is
            // dead work: nf is never read after the last edge update)
            k_node_upd<<<gN, TB>>>(mnW1 + (size_t)r * 512, mnB1 + (size_t)r * 16,
                                   mnW2 + (size_t)r * 256, mnB2 + (size_t)r * 16,
                                   meW1 + (size_t)(r + 1) * 16 * 48,
                                   meB1 + (size_t)(r + 1) * 16);
        }
    }

    int write_extra = (out_size >= 3 * NE) ? 1 : 0;
    k_dec<<<gE, TB>>>(senders, receivers, bi, dW1, dB1, dW2, dB2,
                      (float*)d_out, write_extra);
}